// round 13
// baseline (speedup 1.0000x reference)
#include <cuda_runtime.h>
#include <math.h>

#define BN 16
#define DD 512
#define TT 2048
#define CC 20
#define KK 7
#define FF (CC*KK)            // 140
#define PT 2048
#define TS 32                 // similarity tile
#define EPSV 1e-8f
#define BIGV 1e9f
#define THSIM 0.5f
#define THDIF 0.1f
#define SIM_BLOCKS 592

// -------- scratch (static device globals; no runtime allocation) --------
__device__ float    g_Et[(size_t)BN*DD*PT];   // transposed gathered points [b][d][p]
__device__ int      g_fg_idx[BN*FF];
__device__ int      g_slotmap[BN*TT];
__device__ int      g_sw[BN*PT];
__device__ unsigned char g_sfg[BN*PT];
__device__ unsigned char g_sbg[BN*PT];
__device__ int      g_Nb[BN];
__device__ int      g_bgcnt[BN];
__device__ int      g_sumw[BN];
__device__ int      g_tiles[BN];
__device__ unsigned g_minff[BN*PT];
__device__ unsigned g_maxfb[BN*PT];
__device__ unsigned g_minbb[BN*PT];
__device__ unsigned g_maxbf[BN*PT];
__device__ float    g_perbatch[BN];
__device__ int      g_ticket;

__device__ __forceinline__ unsigned fenc(float f) {
    unsigned u = __float_as_uint(f);
    return (u & 0x80000000u) ? ~u : (u | 0x80000000u);
}
__device__ __forceinline__ float fdec(unsigned x) {
    return (x & 0x80000000u) ? __uint_as_float(x ^ 0x80000000u) : __uint_as_float(~x);
}

#define PACK2(out, lo, hi) asm("mov.b64 %0, {%1, %2};" : "=l"(out) : "f"(lo), "f"(hi))
#define UNPACK2(lo, hi, in) asm("mov.b64 {%0, %1}, %2;" : "=f"(lo), "=f"(hi) : "l"(in))
#define FMA2(d, a, b, c) asm("fma.rn.f32x2 %0, %1, %2, %3;" : "=l"(d) : "l"(a), "l"(b), "l"(c))

// -------- single-pass top-7: per-thread sorted list + tournament merge --------
__global__ void k_topk(const float* __restrict__ cas) {
    int c = blockIdx.x, b = blockIdx.y, tid = threadIdx.x;
    const float* row = cas + ((size_t)b * CC + c) * TT;

    float lv[KK]; int li[KK];
#pragma unroll
    for (int j = 0; j < KK; j++) { lv[j] = -INFINITY; li[j] = 0x7fffffff; }
#pragma unroll
    for (int i = 0; i < 8; i++) {
        int t = tid + i * 256;
        float cv = row[t]; int ci = t;
#pragma unroll
        for (int j = 0; j < KK; j++) {
            bool better = (cv > lv[j]) || (cv == lv[j] && ci < li[j]);
            if (better) { float tv = lv[j]; int ti = li[j]; lv[j] = cv; li[j] = ci; cv = tv; ci = ti; }
        }
    }

    __shared__ float sv[256][KK];
    __shared__ int   si[256][KK];
#pragma unroll
    for (int j = 0; j < KK; j++) { sv[tid][j] = lv[j]; si[tid][j] = li[j]; }

    for (int s = 128; s > 0; s >>= 1) {
        __syncthreads();
        if (tid < s) {
            float mv[KK]; int mi[KK];
            int ia = 0, ib = 0;
#pragma unroll
            for (int j = 0; j < KK; j++) {
                float va = sv[tid][ia],     vb = sv[tid + s][ib];
                int   xa = si[tid][ia],     xb = si[tid + s][ib];
                bool takeA = (va > vb) || (va == vb && xa < xb);
                if (takeA) { mv[j] = va; mi[j] = xa; ia++; }
                else       { mv[j] = vb; mi[j] = xb; ib++; }
            }
#pragma unroll
            for (int j = 0; j < KK; j++) { sv[tid][j] = mv[j]; si[tid][j] = mi[j]; }
        }
    }
    __syncthreads();
    if (tid < KK) g_fg_idx[b * FF + c * KK + tid] = si[0][tid];
}

// -------- prep: unique-point slots, flags, weights, reduction init --------
__global__ void k_prep(const int* __restrict__ click, const int* __restrict__ label,
                       const int* __restrict__ clsnum) {
    int b = blockIdx.x, tid = threadIdx.x;
    int cn = clsnum ? clsnum[0] : CC;
    __shared__ int w[TT];
    __shared__ int woff[8];
    __shared__ int sbase, sbg;
    for (int t = tid; t < TT; t += 256) w[t] = 0;
    unsigned encBig = fenc(BIGV), encNeg = fenc(-BIGV);
    for (int p = tid; p < PT; p += 256) {
        g_minff[b * PT + p] = encBig;
        g_maxfb[b * PT + p] = encNeg;
        g_minbb[b * PT + p] = encBig;
        g_maxbf[b * PT + p] = encNeg;
    }
    if (tid == 0) { sbase = 0; sbg = 0; }
    __syncthreads();
    for (int i = tid; i < FF; i += 256) {
        int c = i / KK;
        if (label[b * CC + c] == 1) atomicAdd(&w[g_fg_idx[b * FF + i]], 1);
    }
    __syncthreads();
    for (int chunk = 0; chunk < TT; chunk += 256) {
        int t = chunk + tid;
        int bg  = (click[b * TT + t] == cn) ? 1 : 0;
        int wt  = w[t];
        int sel = (bg || wt > 0) ? 1 : 0;
        unsigned ball = __ballot_sync(0xffffffffu, sel);
        unsigned ballbg = __ballot_sync(0xffffffffu, bg);
        int wi = tid >> 5, lane = tid & 31;
        if (lane == 0) { woff[wi] = __popc(ball); atomicAdd(&sbg, __popc(ballbg)); }
        __syncthreads();
        if (tid == 0) {
            int s = sbase;
            for (int i = 0; i < 8; i++) { int cc2 = woff[i]; woff[i] = s; s += cc2; }
            sbase = s;
        }
        __syncthreads();
        if (sel) {
            int pos = woff[wi] + __popc(ball & ((1u << lane) - 1u));
            g_slotmap[b * TT + t] = pos;
            g_sw[b * PT + pos] = wt;
            g_sfg[b * PT + pos] = (wt > 0) ? 1 : 0;
            g_sbg[b * PT + pos] = (unsigned char)bg;
        } else {
            g_slotmap[b * TT + t] = -1;
        }
        __syncthreads();
    }
    if (tid == 0) {
        int numpos = 0;
        for (int c = 0; c < CC; c++) numpos += (label[b * CC + c] == 1) ? 1 : 0;
        g_sumw[b]  = KK * numpos;
        g_bgcnt[b] = sbg;
        g_Nb[b]    = sbase;
        g_tiles[b] = (sbase + TS - 1) / TS;
    }
}

// -------- transpose-gather: 4 d-rows/block, 8 loads in flight, shared slotmap --------
__global__ void k_gatherT(const float* __restrict__ emb) {
    int b = blockIdx.y, tid = threadIdx.x;
    int d0 = blockIdx.x * 4;
    __shared__ int smap[TT];
#pragma unroll
    for (int i = 0; i < 8; i++) smap[tid + i * 256] = g_slotmap[b * TT + tid + i * 256];
    __syncthreads();

    const float4* src = (const float4*)(emb + ((size_t)b * DD + d0) * TT);
    float4 v[8];
#pragma unroll
    for (int dd = 0; dd < 4; dd++) {
#pragma unroll
        for (int it = 0; it < 2; it++)
            v[dd * 2 + it] = src[dd * (TT / 4) + tid + it * 256];
    }
    int sA[4], sB[4];
    {
        int t0 = tid * 4, t1 = (tid + 256) * 4;
#pragma unroll
        for (int j = 0; j < 4; j++) { sA[j] = smap[t0 + j]; sB[j] = smap[t1 + j]; }
    }
#pragma unroll
    for (int dd = 0; dd < 4; dd++) {
        float* dst = g_Et + ((size_t)b * DD + d0 + dd) * PT;
        float4 a = v[dd * 2], c = v[dd * 2 + 1];
        if (sA[0] >= 0) dst[sA[0]] = a.x;
        if (sA[1] >= 0) dst[sA[1]] = a.y;
        if (sA[2] >= 0) dst[sA[2]] = a.z;
        if (sA[3] >= 0) dst[sA[3]] = a.w;
        if (sB[0] >= 0) dst[sB[0]] = c.x;
        if (sB[1] >= 0) dst[sB[1]] = c.y;
        if (sB[2] >= 0) dst[sB[2]] = c.z;
        if (sB[3] >= 0) dst[sB[3]] = c.w;
    }
}

// -------- routing helper: one row-quad (4 cosines) per thread --------
__device__ __forceinline__ void route_quad(const float cs[4], int b, int ri, bool rvalid,
                                           const int cfg[4], const int cbg[4], int tx) {
    float vFF = BIGV, vBF = -BIGV, vFB = -BIGV, vBB = BIGV;
#pragma unroll
    for (int j = 0; j < 4; j++) {
        if (cfg[j]) { vFF = fminf(vFF, cs[j]); vBF = fmaxf(vBF, cs[j]); }
        if (cbg[j]) { vFB = fmaxf(vFB, cs[j]); vBB = fminf(vBB, cs[j]); }
    }
#pragma unroll
    for (int m = 4; m > 0; m >>= 1) {
        vFF = fminf(vFF, __shfl_xor_sync(0xffffffffu, vFF, m));
        vBF = fmaxf(vBF, __shfl_xor_sync(0xffffffffu, vBF, m));
        vFB = fmaxf(vFB, __shfl_xor_sync(0xffffffffu, vFB, m));
        vBB = fminf(vBB, __shfl_xor_sync(0xffffffffu, vBB, m));
    }
    if (tx == 0 && rvalid) {
        if (g_sfg[b * PT + ri]) {
            atomicMin(&g_minff[b * PT + ri], fenc(vFF));
            atomicMax(&g_maxfb[b * PT + ri], fenc(vFB));
        }
        if (g_sbg[b * PT + ri]) {
            atomicMax(&g_maxbf[b * PT + ri], fenc(vBF));
            atomicMin(&g_minbb[b * PT + ri], fenc(vBB));
        }
    }
}

// -------- fused symmetric tiled similarity: 8 FREE-RUNNING warps, no mainloop barriers --------
__global__ void __launch_bounds__(256) k_sim() {
    __shared__ float part[8][32][32];       // per-warp k-slice partial tiles (32 KB)
    __shared__ float sqA[8][32], sqB[8][32];
    __shared__ float comb[32][33];
    __shared__ float nrmA[TS], nrmB[TS];
    __shared__ int   s_off[BN + 1];

    int tid = threadIdx.x;
    int w = tid >> 5, lane = tid & 31;
    int ry = lane >> 3;                    // rows [8ry, 8ry+8)
    int cx = lane & 7;                     // cols [4cx, 4cx+4)
    int tx = tid & 7;                      // epilogue col-group

    if (tid == 0) {
        int off = 0;
        for (int b = 0; b < BN; b++) { s_off[b] = off; int t = g_tiles[b]; off += t * (t + 1) / 2; }
        s_off[BN] = off;
    }
    __syncthreads();
    int total = s_off[BN];

    for (int item = blockIdx.x; item < total; item += gridDim.x) {
        int b = 0;
        while (b < BN - 1 && item >= s_off[b + 1]) b++;
        int local = item - s_off[b];
        int tiles = g_tiles[b];
        int rt = 0, rem = local;
        while (rem >= tiles - rt) { rem -= tiles - rt; rt++; }
        int ct = rt + rem;
        int Nb = g_Nb[b];
        int rowb = rt * TS, colb = ct * TS;

        const float* Eb = g_Et + (size_t)b * DD * PT;

        // ---- warp-private mainloop over its 64-d slice (no barriers) ----
        unsigned long long acc2[4][4];     // [row-pair][col]: lo=row 2k, hi=row 2k+1
#pragma unroll
        for (int k = 0; k < 4; k++)
#pragma unroll
            for (int j = 0; j < 4; j++) acc2[k][j] = 0ull;

        const float* pA = Eb + (size_t)(w * 64) * PT + rowb + 8 * ry;
        const float* pB = Eb + (size_t)(w * 64) * PT + colb + 4 * cx;
#pragma unroll 4
        for (int d = 0; d < 64; d++) {
            float4 a0 = *(const float4*)pA;
            float4 a1 = *(const float4*)(pA + 4);
            float4 bv = *(const float4*)pB;
            pA += PT; pB += PT;
            unsigned long long ap0, ap1, ap2, ap3, bp;
            PACK2(ap0, a0.x, a0.y); PACK2(ap1, a0.z, a0.w);
            PACK2(ap2, a1.x, a1.y); PACK2(ap3, a1.z, a1.w);
            PACK2(bp, bv.x, bv.x);
            FMA2(acc2[0][0], ap0, bp, acc2[0][0]); FMA2(acc2[1][0], ap1, bp, acc2[1][0]);
            FMA2(acc2[2][0], ap2, bp, acc2[2][0]); FMA2(acc2[3][0], ap3, bp, acc2[3][0]);
            PACK2(bp, bv.y, bv.y);
            FMA2(acc2[0][1], ap0, bp, acc2[0][1]); FMA2(acc2[1][1], ap1, bp, acc2[1][1]);
            FMA2(acc2[2][1], ap2, bp, acc2[2][1]); FMA2(acc2[3][1], ap3, bp, acc2[3][1]);
            PACK2(bp, bv.z, bv.z);
            FMA2(acc2[0][2], ap0, bp, acc2[0][2]); FMA2(acc2[1][2], ap1, bp, acc2[1][2]);
            FMA2(acc2[2][2], ap2, bp, acc2[2][2]); FMA2(acc2[3][2], ap3, bp, acc2[3][2]);
            PACK2(bp, bv.w, bv.w);
            FMA2(acc2[0][3], ap0, bp, acc2[0][3]); FMA2(acc2[1][3], ap1, bp, acc2[1][3]);
            FMA2(acc2[2][3], ap2, bp, acc2[2][3]); FMA2(acc2[3][3], ap3, bp, acc2[3][3]);
        }

        // ---- warp-private norm pass over its slice (coalesced, L1-hot) ----
        float sa = 0.f, sb = 0.f;
        {
            const float* qA = Eb + (size_t)(w * 64) * PT + rowb + lane;
            const float* qB = Eb + (size_t)(w * 64) * PT + colb + lane;
#pragma unroll 8
            for (int d = 0; d < 64; d++) {
                float va = qA[(size_t)d * PT];
                float vb = qB[(size_t)d * PT];
                sa += va * va; sb += vb * vb;
            }
        }
        sqA[w][lane] = sa;
        sqB[w][lane] = sb;

        // ---- store warp partial tile ----
#pragma unroll
        for (int k = 0; k < 4; k++)
#pragma unroll
            for (int j = 0; j < 4; j++) {
                float lo, hi;
                UNPACK2(lo, hi, acc2[k][j]);
                part[w][8 * ry + 2 * k    ][4 * cx + j] = lo;
                part[w][8 * ry + 2 * k + 1][4 * cx + j] = hi;
            }
        __syncthreads();

        // ---- combine (fixed w0..w7 left fold) + norms ----
        {
            int r = tid >> 3, c4 = (tid & 7) * 4;
            float4 s = *(const float4*)&part[0][r][c4];
#pragma unroll
            for (int w2 = 1; w2 < 8; w2++) {
                float4 t = *(const float4*)&part[w2][r][c4];
                s.x += t.x; s.y += t.y; s.z += t.z; s.w += t.w;
            }
            comb[r][c4] = s.x; comb[r][c4 + 1] = s.y; comb[r][c4 + 2] = s.z; comb[r][c4 + 3] = s.w;
        }
        if (tid < 32) {
            float s = sqA[0][tid];
#pragma unroll
            for (int w2 = 1; w2 < 8; w2++) s += sqA[w2][tid];
            nrmA[tid] = sqrtf(s);
        } else if (tid < 64) {
            int p = tid - 32;
            float s = sqB[0][p];
#pragma unroll
            for (int w2 = 1; w2 < 8; w2++) s += sqB[w2][p];
            nrmB[p] = sqrtf(s);
        }
        __syncthreads();

        // ---- route pass 1: rows = A-points, cols = B-points ----
        {
            int lr = tid >> 3;
            int ri = rowb + lr;
            float nr = nrmA[lr];
            float cs[4]; int cfg[4], cbg[4];
#pragma unroll
            for (int j = 0; j < 4; j++) {
                int lc = 4 * tx + j;
                int c = colb + lc;
                bool cok = (c < Nb);
                cs[j] = comb[lr][lc] / fmaxf(nr * nrmB[lc], EPSV);
                cfg[j] = cok && g_sfg[b * PT + c];
                cbg[j] = cok && g_sbg[b * PT + c];
            }
            route_quad(cs, b, ri, ri < Nb, cfg, cbg, tx);
        }
        // ---- route pass 2 (off-diagonal): rows = B-points, cols = A-points ----
        if (rt != ct) {
            int lr = tid >> 3;
            int ri = colb + lr;
            float nr = nrmB[lr];
            float cs[4]; int cfg[4], cbg[4];
#pragma unroll
            for (int j = 0; j < 4; j++) {
                int lc = 4 * tx + j;
                int c = rowb + lc;
                bool cok = (c < Nb);
                cs[j] = comb[lc][lr] / fmaxf(nr * nrmA[lc], EPSV);
                cfg[j] = cok && g_sfg[b * PT + c];
                cbg[j] = cok && g_sbg[b * PT + c];
            }
            route_quad(cs, b, ri, ri < Nb, cfg, cbg, tx);
        }
        __syncthreads();                   // protect part/comb/sq before next item
    }
}

// -------- per-batch weighted means + fused final (last-block ticket) --------
__global__ void k_batch(float* __restrict__ out) {
    int b = blockIdx.x, tid = threadIdx.x;
    int Nb = g_Nb[b];
    float sff = 0.f, sfb = 0.f, sbb = 0.f, sbf = 0.f;
    for (int p = tid; p < Nb; p += 256) {
        if (g_sfg[b * PT + p]) {
            float wv = (float)g_sw[b * PT + p];
            sff += wv * fmaxf(THSIM - fdec(g_minff[b * PT + p]), 0.f);
            sfb += wv * fmaxf(fdec(g_maxfb[b * PT + p]) - THDIF, 0.f);
        }
        if (g_sbg[b * PT + p]) {
            sbb += fmaxf(THSIM - fdec(g_minbb[b * PT + p]), 0.f);
            sbf += fmaxf(fdec(g_maxbf[b * PT + p]) - THDIF, 0.f);
        }
    }
    __shared__ float r1[256], r2[256], r3[256], r4[256];
    __shared__ int s_last;
    r1[tid] = sff; r2[tid] = sfb; r3[tid] = sbb; r4[tid] = sbf;
    __syncthreads();
    for (int s = 128; s > 0; s >>= 1) {
        if (tid < s) {
            r1[tid] += r1[tid + s]; r2[tid] += r2[tid + s];
            r3[tid] += r3[tid + s]; r4[tid] += r4[tid + s];
        }
        __syncthreads();
    }
    if (tid == 0) {
        int cnt = g_bgcnt[b];
        float denf = fmaxf((float)g_sumw[b], 1.f);
        float denb = fmaxf((float)cnt, 1.f);
        float loss = r1[0] / denf + r2[0] / denf + r3[0] / denb + r4[0] / denb;
        g_perbatch[b] = (cnt > 0) ? loss : 0.f;
        __threadfence();
        int old = atomicAdd(&g_ticket, 1);
        s_last = (old == BN - 1) ? 1 : 0;
    }
    __syncthreads();
    if (s_last && tid == 0) {
        volatile float* pb = g_perbatch;
        float s = 0.f; int c = 0;
        for (int bb = 0; bb < BN; bb++) { s += pb[bb]; if (g_bgcnt[bb] > 0) c++; }
        out[0] = s / fmaxf((float)c, 1.f);
        g_ticket = 0;   // reset for next graph replay
    }
}

extern "C" void kernel_launch(void* const* d_in, const int* in_sizes, int n_in,
                              void* d_out, int out_size) {
    const float* emb    = (const float*)d_in[0];
    const float* cas    = (const float*)d_in[1];
    const int*   click  = (const int*)d_in[2];
    const int*   label  = (const int*)d_in[3];
    const int*   clsnum = (n_in >= 5) ? (const int*)d_in[4] : nullptr;

    k_topk   <<<dim3(CC, BN), 256>>>(cas);
    k_prep   <<<BN, 256>>>(click, label, clsnum);
    k_gatherT<<<dim3(DD / 4, BN), 256>>>(emb);
    k_sim    <<<SIM_BLOCKS, 256>>>();
    k_batch  <<<BN, 256>>>((float*)d_out);
}